// round 2
// baseline (speedup 1.0000x reference)
#include <cuda_runtime.h>
#include <math.h>

// Problem constants
#define BB 4
#define TT 1024
#define DD 1024
#define HH 16
#define DKK 64
#define MROWS (BB*TT)   // 4096

// Scratch (static device globals; no allocation allowed)
__device__ float g_Q[BB*HH*TT*DKK];     // [B,H,T,DK] 16MB
__device__ float g_K[BB*HH*TT*DKK];
__device__ float g_V[BB*HH*TT*DKK];
__device__ float g_attn[BB*TT*DD];      // [B,T,D]
__device__ float g_vmean[BB*HH*DKK];
__device__ float g_c[BB];
__device__ float g_scale[BB];           // 1/(8*tau_b)

// ---------------------------------------------------------------------------
// NT SGEMM: C[i,j] = sum_k A[i,k]*W[j,k] + bias[j]
// A: [4096,1024] rowmajor, W: [1024,1024] rowmajor. BM=BN=128, BK=8, 256 thr.
// MODE 0: C rowmajor [4096,1024]. MODE 1: write [B,H,T,DK] layout.
// ---------------------------------------------------------------------------
template<int MODE>
__global__ __launch_bounds__(256)
void sgemm_nt(const float* __restrict__ A, const float* __restrict__ W,
              const float* __restrict__ bias, float* __restrict__ C) {
    const int K = 1024, N = 1024;
    __shared__ float As[8][128];
    __shared__ float Bs[8][128];
    int tid = threadIdx.x;
    int bm = blockIdx.y * 128, bn = blockIdx.x * 128;
    int lrow = tid >> 1;
    int lcol = (tid & 1) * 4;
    const float* Aptr = A + (size_t)(bm + lrow) * K + lcol;
    const float* Wptr = W + (size_t)(bn + lrow) * K + lcol;
    int tyy = tid >> 4, txx = tid & 15;
    int tm = tyy * 8, tn = txx * 8;
    float acc[8][8];
#pragma unroll
    for (int i = 0; i < 8; i++)
#pragma unroll
        for (int j = 0; j < 8; j++) acc[i][j] = 0.f;

    for (int kt = 0; kt < K; kt += 8) {
        float4 av = *(const float4*)(Aptr + kt);
        float4 bv = *(const float4*)(Wptr + kt);
        As[lcol+0][lrow] = av.x; As[lcol+1][lrow] = av.y;
        As[lcol+2][lrow] = av.z; As[lcol+3][lrow] = av.w;
        Bs[lcol+0][lrow] = bv.x; Bs[lcol+1][lrow] = bv.y;
        Bs[lcol+2][lrow] = bv.z; Bs[lcol+3][lrow] = bv.w;
        __syncthreads();
#pragma unroll
        for (int k = 0; k < 8; k++) {
            float a[8], b[8];
            *(float4*)&a[0] = *(const float4*)&As[k][tm];
            *(float4*)&a[4] = *(const float4*)&As[k][tm+4];
            *(float4*)&b[0] = *(const float4*)&Bs[k][tn];
            *(float4*)&b[4] = *(const float4*)&Bs[k][tn+4];
#pragma unroll
            for (int i = 0; i < 8; i++)
#pragma unroll
                for (int j = 0; j < 8; j++)
                    acc[i][j] = fmaf(a[i], b[j], acc[i][j]);
        }
        __syncthreads();
    }

#pragma unroll
    for (int i = 0; i < 8; i++) {
        int row = bm + tm + i;
#pragma unroll
        for (int j = 0; j < 8; j++) {
            int col = bn + tn + j;
            float v = acc[i][j] + bias[col];
            if (MODE == 0) {
                C[(size_t)row * N + col] = v;
            } else {
                int b = row >> 10, t = row & 1023;
                int h = col >> 6,  dk = col & 63;
                C[(((size_t)(b*HH + h))*TT + t)*DKK + dk] = v;
            }
        }
    }
}

// ---------------------------------------------------------------------------
// Gate: c, scale=1/(8*tau), u = 1-c. One block per batch.
// ---------------------------------------------------------------------------
__global__ void gate_kernel(const float* __restrict__ Q,
                            const float* __restrict__ Wg1, const float* __restrict__ bg1,
                            const float* __restrict__ Wg2, const float* __restrict__ bg2,
                            float* __restrict__ c_out, float* __restrict__ scale_out,
                            float* __restrict__ u_out, int write_u) {
    int b = blockIdx.x;
    float s1 = 0.f, s2 = 0.f;
    for (int d = threadIdx.x; d < DD; d += 256) {
        // context[d] = Q[b, h=d>>6, t=0, dk=d&63]
        float q = Q[((size_t)(b*HH + (d >> 6)))*TT*DKK + (d & 63)];
        s1 += q * Wg1[d];
        s2 += q * Wg2[d];
    }
#pragma unroll
    for (int off = 16; off >= 1; off >>= 1) {
        s1 += __shfl_xor_sync(0xffffffffu, s1, off);
        s2 += __shfl_xor_sync(0xffffffffu, s2, off);
    }
    __shared__ float r1[8], r2[8];
    int lane = threadIdx.x & 31, w = threadIdx.x >> 5;
    if (lane == 0) { r1[w] = s1; r2[w] = s2; }
    __syncthreads();
    if (threadIdx.x == 0) {
        float t1 = 0.f, t2 = 0.f;
        for (int i = 0; i < 8; i++) { t1 += r1[i]; t2 += r2[i]; }
        float z1 = t1 + bg1[0], z2 = t2 + bg2[0];
        float q1 = 1.f / (1.f + expf(-z1));
        float q2 = 1.f / (1.f + expf(-z2));
        float c = fminf(fmaxf(q1 * q2, 1e-8f), 1.0f);
        float tau = (c < 0.3f) ? (1.0f / c) : 1.0f;
        c_out[b] = c;
        scale_out[b] = 1.0f / (8.0f * tau);   // 1/(sqrt(64)*tau)
        if (write_u) u_out[b] = 1.0f - c;
    }
}

// ---------------------------------------------------------------------------
// V mean over T for each (b,h,dk). 64 blocks, 256 threads.
// ---------------------------------------------------------------------------
__global__ void vmean_kernel(const float* __restrict__ V, float* __restrict__ vmean) {
    __shared__ float sm[256];
    int bh = blockIdx.x, tid = threadIdx.x;
    int dk = tid & 63, part = tid >> 6;
    size_t base = (size_t)bh * TT * DKK;
    float s = 0.f;
    for (int t = part; t < TT; t += 4) s += V[base + (size_t)t * DKK + dk];
    sm[tid] = s;
    __syncthreads();
    if (part == 0)
        vmean[bh*DKK + dk] = (sm[dk] + sm[64+dk] + sm[128+dk] + sm[192+dk]) * (1.0f/1024.0f);
}

// ---------------------------------------------------------------------------
// Flash attention: block = (b,h, 128-query tile). 256 threads.
// Thread tile: 8 q-rows x 4 k-cols (S) / 8 q-rows x 4 dk-cols (O).
// Row softmax state reduced with width-16 shuffles.
// out = c * softmax(Q'K^T) V + (1-c) * vmean, Q' pre-scaled by 1/(8*tau).
// ---------------------------------------------------------------------------
__global__ __launch_bounds__(256)
void attn_kernel(const float* __restrict__ Qg, const float* __restrict__ Kg,
                 const float* __restrict__ Vg, const float* __restrict__ vmean,
                 const float* __restrict__ c_arr, const float* __restrict__ scale_arr,
                 float* __restrict__ out) {
    extern __shared__ float smx[];
    float* Qs = smx;                 // 128*65
    float* Ps = Qs + 128*65;         // 128*65
    float* Ks = Ps + 128*65;         // 64*65
    float* Vs = Ks + 64*65;          // 64*65

    int tid = threadIdx.x;
    int bh = blockIdx.y;
    int b = bh >> 4, h = bh & 15;
    int q0 = blockIdx.x * 128;
    float scale = scale_arr[b];
    float cg = c_arr[b];
    size_t base = (size_t)bh * TT * DKK;

    // Load Q tile (scaled)
#pragma unroll
    for (int it = 0; it < 8; it++) {
        int e = it * 256 + tid;
        int r = e >> 4, c4 = (e & 15) * 4;
        float4 v = *(const float4*)(Qg + base + (size_t)(q0 + r) * 64 + c4);
        float* dst = Qs + r * 65 + c4;
        dst[0] = v.x * scale; dst[1] = v.y * scale;
        dst[2] = v.z * scale; dst[3] = v.w * scale;
    }

    int tyy = tid >> 4, txx = tid & 15;
    int qr = tyy * 8;     // query row base within tile
    int kc = txx * 4;     // k col (and dk col) base

    float m[8], l[8], O[8][4];
#pragma unroll
    for (int i = 0; i < 8; i++) {
        m[i] = -1e30f; l[i] = 0.f;
#pragma unroll
        for (int j = 0; j < 4; j++) O[i][j] = 0.f;
    }

    for (int kt = 0; kt < 16; kt++) {
        int k0 = kt * 64;
#pragma unroll
        for (int it = 0; it < 4; it++) {
            int e = it * 256 + tid;
            int r = e >> 4, c4 = (e & 15) * 4;
            float4 kv = *(const float4*)(Kg + base + (size_t)(k0 + r) * 64 + c4);
            float4 vv = *(const float4*)(Vg + base + (size_t)(k0 + r) * 64 + c4);
            float* kd = Ks + r * 65 + c4;
            kd[0] = kv.x; kd[1] = kv.y; kd[2] = kv.z; kd[3] = kv.w;
            float* vd = Vs + r * 65 + c4;
            vd[0] = vv.x; vd[1] = vv.y; vd[2] = vv.z; vd[3] = vv.w;
        }
        __syncthreads();   // also covers initial Q load on first iter

        float S[8][4];
#pragma unroll
        for (int i = 0; i < 8; i++)
#pragma unroll
            for (int j = 0; j < 4; j++) S[i][j] = 0.f;

#pragma unroll 4
        for (int d = 0; d < 64; d++) {
            float bb0 = Ks[(kc+0)*65 + d];
            float bb1 = Ks[(kc+1)*65 + d];
            float bb2 = Ks[(kc+2)*65 + d];
            float bb3 = Ks[(kc+3)*65 + d];
#pragma unroll
            for (int i = 0; i < 8; i++) {
                float a = Qs[(qr+i)*65 + d];
                S[i][0] = fmaf(a, bb0, S[i][0]);
                S[i][1] = fmaf(a, bb1, S[i][1]);
                S[i][2] = fmaf(a, bb2, S[i][2]);
                S[i][3] = fmaf(a, bb3, S[i][3]);
            }
        }

        // online softmax update per row (16 lanes own one row-group)
#pragma unroll
        for (int i = 0; i < 8; i++) {
            float mt = fmaxf(fmaxf(S[i][0], S[i][1]), fmaxf(S[i][2], S[i][3]));
            mt = fmaxf(mt, __shfl_xor_sync(0xffffffffu, mt, 8, 16));
            mt = fmaxf(mt, __shfl_xor_sync(0xffffffffu, mt, 4, 16));
            mt = fmaxf(mt, __shfl_xor_sync(0xffffffffu, mt, 2, 16));
            mt = fmaxf(mt, __shfl_xor_sync(0xffffffffu, mt, 1, 16));
            float mn = fmaxf(m[i], mt);
            float f = __expf(m[i] - mn);
            float ls = 0.f;
#pragma unroll
            for (int j = 0; j < 4; j++) {
                float p = __expf(S[i][j] - mn);
                S[i][j] = p;
                ls += p;
            }
            ls += __shfl_xor_sync(0xffffffffu, ls, 8, 16);
            ls += __shfl_xor_sync(0xffffffffu, ls, 4, 16);
            ls += __shfl_xor_sync(0xffffffffu, ls, 2, 16);
            ls += __shfl_xor_sync(0xffffffffu, ls, 1, 16);
            l[i] = l[i] * f + ls;
            m[i] = mn;
#pragma unroll
            for (int j = 0; j < 4; j++) O[i][j] *= f;
            float* pr = Ps + (qr + i) * 65 + kc;
            pr[0] = S[i][0]; pr[1] = S[i][1]; pr[2] = S[i][2]; pr[3] = S[i][3];
        }
        __syncthreads();

        // O += P @ V
#pragma unroll 4
        for (int k = 0; k < 64; k++) {
            float v0 = Vs[k*65 + kc + 0];
            float v1 = Vs[k*65 + kc + 1];
            float v2 = Vs[k*65 + kc + 2];
            float v3 = Vs[k*65 + kc + 3];
#pragma unroll
            for (int i = 0; i < 8; i++) {
                float p = Ps[(qr+i)*65 + k];
                O[i][0] = fmaf(p, v0, O[i][0]);
                O[i][1] = fmaf(p, v1, O[i][1]);
                O[i][2] = fmaf(p, v2, O[i][2]);
                O[i][3] = fmaf(p, v3, O[i][3]);
            }
        }
        __syncthreads();
    }

    float one_minus_c = 1.0f - cg;
#pragma unroll
    for (int i = 0; i < 8; i++) {
        float inv = 1.0f / l[i];
        int q = q0 + qr + i;
#pragma unroll
        for (int j = 0; j < 4; j++) {
            int dk = kc + j;
            out[((size_t)b * TT + q) * DD + h * DKK + dk] =
                cg * O[i][j] * inv + one_minus_c * vmean[bh * DKK + dk];
        }
    }
}

// ---------------------------------------------------------------------------
extern "C" void kernel_launch(void* const* d_in, const int* in_sizes, int n_in,
                              void* d_out, int out_size) {
    const float* x   = (const float*)d_in[0];
    const float* Wq  = (const float*)d_in[1];
    const float* bq  = (const float*)d_in[2];
    const float* Wk  = (const float*)d_in[3];
    const float* bk  = (const float*)d_in[4];
    const float* Wv  = (const float*)d_in[5];
    const float* bv  = (const float*)d_in[6];
    const float* Wo  = (const float*)d_in[7];
    const float* bo  = (const float*)d_in[8];
    const float* Wg1 = (const float*)d_in[9];
    const float* bg1 = (const float*)d_in[10];
    const float* Wg2 = (const float*)d_in[11];
    const float* bg2 = (const float*)d_in[12];
    float* out = (float*)d_out;

    float *pQ, *pK, *pV, *pAttn, *pVm, *pC, *pS;
    cudaGetSymbolAddress((void**)&pQ, g_Q);
    cudaGetSymbolAddress((void**)&pK, g_K);
    cudaGetSymbolAddress((void**)&pV, g_V);
    cudaGetSymbolAddress((void**)&pAttn, g_attn);
    cudaGetSymbolAddress((void**)&pVm, g_vmean);
    cudaGetSymbolAddress((void**)&pC, g_c);
    cudaGetSymbolAddress((void**)&pS, g_scale);

    dim3 gemm_grid(1024/128, MROWS/128);   // (8, 32)
    sgemm_nt<1><<<gemm_grid, 256>>>(x, Wq, bq, pQ);
    sgemm_nt<1><<<gemm_grid, 256>>>(x, Wk, bk, pK);
    sgemm_nt<1><<<gemm_grid, 256>>>(x, Wv, bv, pV);

    int write_u = (out_size >= BB*TT*DD + BB) ? 1 : 0;
    gate_kernel<<<BB, 256>>>(pQ, Wg1, bg1, Wg2, bg2, pC, pS,
                             out + (size_t)BB*TT*DD, write_u);
    vmean_kernel<<<BB*HH, 256>>>(pV, pVm);

    const int attn_smem = (128*65 + 128*65 + 64*65 + 64*65) * 4; // 99840 B
    cudaFuncSetAttribute(attn_kernel, cudaFuncAttributeMaxDynamicSharedMemorySize, attn_smem);
    dim3 attn_grid(TT/128, BB*HH);          // (8, 64)
    attn_kernel<<<attn_grid, 256, attn_smem>>>(pQ, pK, pV, pVm, pC, pS, pAttn);

    sgemm_nt<0><<<gemm_grid, 256>>>(pAttn, Wo, bo, out);
}

// round 4
// speedup vs baseline: 1.8085x; 1.8085x over previous
#include <cuda_runtime.h>
#include <cuda_bf16.h>
#include <math.h>
#include <stdint.h>

#define BB 4
#define TT 1024
#define DD 1024
#define HH 16
#define DKK 64
#define MROWS (BB*TT)   // 4096

// ---------------- scratch (static device globals) ----------------
__device__ float g_Q[BB*HH*TT*DKK];
__device__ float g_K[BB*HH*TT*DKK];
__device__ float g_V[BB*HH*TT*DKK];
__device__ float g_vmean[BB*HH*DKK];
__device__ float g_c[BB];
__device__ float g_scale[BB];
__device__ __nv_bfloat16 g_xh[MROWS*DD], g_xl[MROWS*DD];
__device__ __nv_bfloat16 g_WhQ[DD*DD], g_WlQ[DD*DD];
__device__ __nv_bfloat16 g_WhK[DD*DD], g_WlK[DD*DD];
__device__ __nv_bfloat16 g_WhV[DD*DD], g_WlV[DD*DD];
__device__ __nv_bfloat16 g_WhO[DD*DD], g_WlO[DD*DD];
__device__ __nv_bfloat16 g_aH[MROWS*DD], g_aL[MROWS*DD];

// ---------------- PTX helpers (sm_80-era only: safe on compute_103) --------
__device__ __forceinline__ uint32_t smem_u32(const void* p) {
    uint32_t a;
    asm("{ .reg .u64 t; cvta.to.shared.u64 t, %1; cvt.u32.u64 %0, t; }" : "=r"(a) : "l"(p));
    return a;
}
#define CP_ASYNC16(dst, src) asm volatile("cp.async.cg.shared.global [%0], [%1], 16;" :: "r"(dst), "l"(src))
#define CP_COMMIT()          asm volatile("cp.async.commit_group;" ::: "memory")
#define CP_WAIT(n)           asm volatile("cp.async.wait_group %0;" :: "n"(n) : "memory")

__device__ __forceinline__ void ldsm_x4(uint32_t& r0, uint32_t& r1, uint32_t& r2, uint32_t& r3, uint32_t addr) {
    asm volatile("ldmatrix.sync.aligned.m8n8.x4.shared.b16 {%0,%1,%2,%3}, [%4];"
                 : "=r"(r0), "=r"(r1), "=r"(r2), "=r"(r3) : "r"(addr));
}
__device__ __forceinline__ void ldsm_x2(uint32_t& r0, uint32_t& r1, uint32_t addr) {
    asm volatile("ldmatrix.sync.aligned.m8n8.x2.shared.b16 {%0,%1}, [%2];"
                 : "=r"(r0), "=r"(r1) : "r"(addr));
}
__device__ __forceinline__ void mma16816(float* d, const uint32_t* a, const uint32_t* b) {
    asm volatile("mma.sync.aligned.m16n8k16.row.col.f32.bf16.bf16.f32 "
                 "{%0,%1,%2,%3},{%4,%5,%6,%7},{%8,%9},{%0,%1,%2,%3};"
                 : "+f"(d[0]), "+f"(d[1]), "+f"(d[2]), "+f"(d[3])
                 : "r"(a[0]), "r"(a[1]), "r"(a[2]), "r"(a[3]), "r"(b[0]), "r"(b[1]));
}

// ---------------------------------------------------------------------------
// Split-bf16 warp-MMA GEMM: C[m,n] = sum_k A[m,k]*W[n,k] + bias[n]
// CTA tile 128x128, BK=64 (128B rows, xor-swizzled), 8 warps (64x32 each),
// cp.async double buffer. MODE 0: C rowmajor. MODE 1: [B,H,T,DK] scatter.
// ---------------------------------------------------------------------------
struct GemmArgs {
    const __nv_bfloat16 *Ah, *Al;
    const __nv_bfloat16 *Wh0, *Wl0, *Wh1, *Wl1, *Wh2, *Wl2;
    const float *b0, *b1, *b2;
    float *C0, *C1, *C2;
};

// stage layout: Ah @0, Al @16K, Wh @32K, Wl @48K; stage stride 64K
__device__ __forceinline__ void load_stage(uint32_t sbase, int tid,
                                           const __nv_bfloat16* Ah, const __nv_bfloat16* Al,
                                           const __nv_bfloat16* Wh, const __nv_bfloat16* Wl,
                                           int bm, int bn, int k0) {
#pragma unroll
    for (int i = 0; i < 4; i++) {
        int g = tid + i * 256;           // 0..1023
        int r = g >> 3;                  // row 0..127
        int c = g & 7;                   // 16B chunk 0..7
        uint32_t sw = (uint32_t)(r * 128 + (((c ^ (r & 7))) << 4));
        size_t ga = (size_t)(bm + r) * 1024 + k0;
        size_t gw = (size_t)(bn + r) * 1024 + k0;
        CP_ASYNC16(sbase +     0 + sw, (const char*)(Ah + ga) + c * 16);
        CP_ASYNC16(sbase + 16384 + sw, (const char*)(Al + ga) + c * 16);
        CP_ASYNC16(sbase + 32768 + sw, (const char*)(Wh + gw) + c * 16);
        CP_ASYNC16(sbase + 49152 + sw, (const char*)(Wl + gw) + c * 16);
    }
}

__device__ __forceinline__ void compute_stage(uint32_t base, int wm, int wn, int lane,
                                              float acc[4][4][4]) {
    const uint32_t aH = base, aL = base + 16384, bH = base + 32768, bL = base + 49152;
    const int rA = wm + (lane & 15);
    const int hA = lane >> 4;
    const int rB = wn + (lane & 7);
    const int hB = (lane >> 3) & 1;
#pragma unroll
    for (int ks = 0; ks < 4; ks++) {
        uint32_t Af[4][4], Alf[4][4], Bf[4][2], Blf[4][2];
#pragma unroll
        for (int mt = 0; mt < 4; mt++) {
            int r = rA + mt * 16;
            uint32_t off = (uint32_t)(r * 128 + ((((ks * 2 + hA)) ^ (r & 7)) << 4));
            ldsm_x4(Af[mt][0], Af[mt][1], Af[mt][2], Af[mt][3], aH + off);
            ldsm_x4(Alf[mt][0], Alf[mt][1], Alf[mt][2], Alf[mt][3], aL + off);
        }
#pragma unroll
        for (int nt = 0; nt < 4; nt++) {
            int r = rB + nt * 8;
            uint32_t off = (uint32_t)(r * 128 + ((((ks * 2 + hB)) ^ (r & 7)) << 4));
            ldsm_x2(Bf[nt][0], Bf[nt][1], bH + off);
            ldsm_x2(Blf[nt][0], Blf[nt][1], bL + off);
        }
#pragma unroll
        for (int mt = 0; mt < 4; mt++)
#pragma unroll
            for (int nt = 0; nt < 4; nt++) {
                mma16816(acc[mt][nt], Af[mt], Bf[nt]);
                mma16816(acc[mt][nt], Af[mt], Blf[nt]);
                mma16816(acc[mt][nt], Alf[mt], Bf[nt]);
            }
    }
}

template<int MODE>
__global__ __launch_bounds__(256)
void gemm_mma(GemmArgs args) {
    extern __shared__ char smem[];
    const int tid = threadIdx.x, wid = tid >> 5, lane = tid & 31;
    const int z = blockIdx.z;
    const __nv_bfloat16* Ah = args.Ah;
    const __nv_bfloat16* Al = args.Al;
    const __nv_bfloat16* Wh = (z == 0) ? args.Wh0 : (z == 1) ? args.Wh1 : args.Wh2;
    const __nv_bfloat16* Wl = (z == 0) ? args.Wl0 : (z == 1) ? args.Wl1 : args.Wl2;
    const float* bias = (z == 0) ? args.b0 : (z == 1) ? args.b1 : args.b2;
    float* C = (z == 0) ? args.C0 : (z == 1) ? args.C1 : args.C2;

    const int bm = blockIdx.y * 128, bn = blockIdx.x * 128;
    const int wm = (wid >> 2) * 64, wn = (wid & 3) * 32;
    const uint32_t s0 = smem_u32(smem);

    float acc[4][4][4];
#pragma unroll
    for (int a = 0; a < 4; a++)
#pragma unroll
        for (int b = 0; b < 4; b++)
#pragma unroll
            for (int c = 0; c < 4; c++) acc[a][b][c] = 0.f;

    load_stage(s0, tid, Ah, Al, Wh, Wl, bm, bn, 0);
    CP_COMMIT();

    for (int kt = 0; kt < 16; kt++) {
        const int s = kt & 1;
        if (kt + 1 < 16) {
            load_stage(s0 + ((kt + 1) & 1) * 65536, tid, Ah, Al, Wh, Wl, bm, bn, (kt + 1) * 64);
            CP_COMMIT();
            CP_WAIT(1);
        } else {
            CP_WAIT(0);
        }
        __syncthreads();
        compute_stage(s0 + s * 65536, wm, wn, lane, acc);
        __syncthreads();
    }

    // Epilogue: direct stores with bias
    const int lr = lane >> 2, lc = (lane & 3) * 2;
#pragma unroll
    for (int mt = 0; mt < 4; mt++) {
#pragma unroll
        for (int nt = 0; nt < 4; nt++) {
            int c0 = bn + wn + nt * 8 + lc;
            float b0 = __ldg(bias + c0), b1 = __ldg(bias + c0 + 1);
            int r0 = bm + wm + mt * 16 + lr;
            int r1 = r0 + 8;
            float2 v0 = make_float2(acc[mt][nt][0] + b0, acc[mt][nt][1] + b1);
            float2 v1 = make_float2(acc[mt][nt][2] + b0, acc[mt][nt][3] + b1);
            if (MODE == 0) {
                *(float2*)(C + (size_t)r0 * 1024 + c0) = v0;
                *(float2*)(C + (size_t)r1 * 1024 + c0) = v1;
            } else {
                int h = c0 >> 6, dk = c0 & 63;
                int b_0 = r0 >> 10, t_0 = r0 & 1023;
                int b_1 = r1 >> 10, t_1 = r1 & 1023;
                *(float2*)(C + (((size_t)(b_0 * HH + h)) * TT + t_0) * DKK + dk) = v0;
                *(float2*)(C + (((size_t)(b_1 * HH + h)) * TT + t_1) * DKK + dk) = v1;
            }
        }
    }
}

// ---------------------------------------------------------------------------
// fp32 -> bf16 hi/lo split conversion
// ---------------------------------------------------------------------------
__global__ void convert_hl(const float* __restrict__ src,
                           __nv_bfloat16* __restrict__ h,
                           __nv_bfloat16* __restrict__ l, int n4) {
    int i = blockIdx.x * 256 + threadIdx.x;
    if (i >= n4) return;
    float4 v = ((const float4*)src)[i];
    __nv_bfloat16 h0 = __float2bfloat16(v.x);
    __nv_bfloat16 h1 = __float2bfloat16(v.y);
    __nv_bfloat16 h2 = __float2bfloat16(v.z);
    __nv_bfloat16 h3 = __float2bfloat16(v.w);
    __nv_bfloat162 hp0; hp0.x = h0; hp0.y = h1;
    __nv_bfloat162 hp1; hp1.x = h2; hp1.y = h3;
    ((__nv_bfloat162*)h)[i * 2 + 0] = hp0;
    ((__nv_bfloat162*)h)[i * 2 + 1] = hp1;
    __nv_bfloat162 lp0, lp1;
    lp0.x = __float2bfloat16(v.x - __bfloat162float(h0));
    lp0.y = __float2bfloat16(v.y - __bfloat162float(h1));
    lp1.x = __float2bfloat16(v.z - __bfloat162float(h2));
    lp1.y = __float2bfloat16(v.w - __bfloat162float(h3));
    ((__nv_bfloat162*)l)[i * 2 + 0] = lp0;
    ((__nv_bfloat162*)l)[i * 2 + 1] = lp1;
}

// ---------------------------------------------------------------------------
// Gate: c, scale=1/(8*tau), u = 1-c. One block per batch.
// ---------------------------------------------------------------------------
__global__ void gate_kernel(const float* __restrict__ Q,
                            const float* __restrict__ Wg1, const float* __restrict__ bg1,
                            const float* __restrict__ Wg2, const float* __restrict__ bg2,
                            float* __restrict__ c_out, float* __restrict__ scale_out,
                            float* __restrict__ u_out, int write_u) {
    int b = blockIdx.x;
    float s1 = 0.f, s2 = 0.f;
    for (int d = threadIdx.x; d < DD; d += 256) {
        float q = Q[((size_t)(b*HH + (d >> 6)))*TT*DKK + (d & 63)];
        s1 += q * Wg1[d];
        s2 += q * Wg2[d];
    }
#pragma unroll
    for (int off = 16; off >= 1; off >>= 1) {
        s1 += __shfl_xor_sync(0xffffffffu, s1, off);
        s2 += __shfl_xor_sync(0xffffffffu, s2, off);
    }
    __shared__ float r1[8], r2[8];
    int lane = threadIdx.x & 31, w = threadIdx.x >> 5;
    if (lane == 0) { r1[w] = s1; r2[w] = s2; }
    __syncthreads();
    if (threadIdx.x == 0) {
        float t1 = 0.f, t2 = 0.f;
        for (int i = 0; i < 8; i++) { t1 += r1[i]; t2 += r2[i]; }
        float z1 = t1 + bg1[0], z2 = t2 + bg2[0];
        float q1 = 1.f / (1.f + expf(-z1));
        float q2 = 1.f / (1.f + expf(-z2));
        float c = fminf(fmaxf(q1 * q2, 1e-8f), 1.0f);
        float tau = (c < 0.3f) ? (1.0f / c) : 1.0f;
        c_out[b] = c;
        scale_out[b] = 1.0f / (8.0f * tau);
        if (write_u) u_out[b] = 1.0f - c;
    }
}

// ---------------------------------------------------------------------------
__global__ void vmean_kernel(const float* __restrict__ V, float* __restrict__ vmean) {
    __shared__ float sm[256];
    int bh = blockIdx.x, tid = threadIdx.x;
    int dk = tid & 63, part = tid >> 6;
    size_t base = (size_t)bh * TT * DKK;
    float s = 0.f;
    for (int t = part; t < TT; t += 4) s += V[base + (size_t)t * DKK + dk];
    sm[tid] = s;
    __syncthreads();
    if (part == 0)
        vmean[bh*DKK + dk] = (sm[dk] + sm[64+dk] + sm[128+dk] + sm[192+dk]) * (1.0f/1024.0f);
}

// ---------------------------------------------------------------------------
// Flash attention (SIMT), epilogue writes split-bf16 for the O projection.
// ---------------------------------------------------------------------------
__global__ __launch_bounds__(256)
void attn_kernel(const float* __restrict__ Qg, const float* __restrict__ Kg,
                 const float* __restrict__ Vg, const float* __restrict__ vmean,
                 const float* __restrict__ c_arr, const float* __restrict__ scale_arr,
                 __nv_bfloat16* __restrict__ outH, __nv_bfloat16* __restrict__ outL) {
    extern __shared__ float smx[];
    float* Qs = smx;                 // 128*65
    float* Ps = Qs + 128*65;         // 128*65
    float* Ks = Ps + 128*65;         // 64*65
    float* Vs = Ks + 64*65;          // 64*65

    int tid = threadIdx.x;
    int bh = blockIdx.y;
    int b = bh >> 4, h = bh & 15;
    int q0 = blockIdx.x * 128;
    float scale = scale_arr[b];
    float cg = c_arr[b];
    size_t base = (size_t)bh * TT * DKK;

#pragma unroll
    for (int it = 0; it < 8; it++) {
        int e = it * 256 + tid;
        int r = e >> 4, c4 = (e & 15) * 4;
        float4 v = *(const float4*)(Qg + base + (size_t)(q0 + r) * 64 + c4);
        float* dst = Qs + r * 65 + c4;
        dst[0] = v.x * scale; dst[1] = v.y * scale;
        dst[2] = v.z * scale; dst[3] = v.w * scale;
    }

    int tyy = tid >> 4, txx = tid & 15;
    int qr = tyy * 8;
    int kc = txx * 4;

    float m[8], l[8], O[8][4];
#pragma unroll
    for (int i = 0; i < 8; i++) {
        m[i] = -1e30f; l[i] = 0.f;
#pragma unroll
        for (int j = 0; j < 4; j++) O[i][j] = 0.f;
    }

    for (int kt = 0; kt < 16; kt++) {
        int k0 = kt * 64;
#pragma unroll
        for (int it = 0; it < 4; it++) {
            int e = it * 256 + tid;
            int r = e >> 4, c4 = (e & 15) * 4;
            float4 kv = *(const float4*)(Kg + base + (size_t)(k0 + r) * 64 + c4);
            float4 vv = *(const float4*)(Vg + base + (size_t)(k0 + r) * 64 + c4);
            float* kd = Ks + r * 65 + c4;
            kd[0] = kv.x; kd[1] = kv.y; kd[2] = kv.z; kd[3] = kv.w;
            float* vd = Vs + r * 65 + c4;
            vd[0] = vv.x; vd[1] = vv.y; vd[2] = vv.z; vd[3] = vv.w;
        }
        __syncthreads();

        float S[8][4];
#pragma unroll
        for (int i = 0; i < 8; i++)
#pragma unroll
            for (int j = 0; j < 4; j++) S[i][j] = 0.f;

#pragma unroll 4
        for (int d = 0; d < 64; d++) {
            float bb0 = Ks[(kc+0)*65 + d];
            float bb1 = Ks[(kc+1)*65 + d];
            float bb2 = Ks[(kc+2)*65 + d];
            float bb3 = Ks[(kc+3)*65 + d];
#pragma unroll
            for (int i = 0; i < 8; i++) {
                float a = Qs[(qr+i)*65 + d];
                S[i][0] = fmaf(a, bb0, S[i][0]);
                S[i][1] = fmaf(a, bb1, S[i][1]);
                S[i][2] = fmaf(a, bb2, S[i][2]);
                S[i][3] = fmaf(a, bb3, S[i][3]);
            }
        }

#pragma unroll
        for (int i = 0; i < 8; i++) {
            float mt = fmaxf(fmaxf(S[i][0], S[i][1]), fmaxf(S[i][2], S[i][3]));
            mt = fmaxf(mt, __shfl_xor_sync(0xffffffffu, mt, 8, 16));
            mt = fmaxf(mt, __shfl_xor_sync(0xffffffffu, mt, 4, 16));
            mt = fmaxf(mt, __shfl_xor_sync(0xffffffffu, mt, 2, 16));
            mt = fmaxf(mt, __shfl_xor_sync(0xffffffffu, mt, 1, 16));
            float mn = fmaxf(m[i], mt);
            float f = __expf(m[i] - mn);
            float ls = 0.f;
#pragma unroll
            for (int j = 0; j < 4; j++) {
                float p = __expf(S[i][j] - mn);
                S[i][j] = p;
                ls += p;
            }
            ls += __shfl_xor_sync(0xffffffffu, ls, 8, 16);
            ls += __shfl_xor_sync(0xffffffffu, ls, 4, 16);
            ls += __shfl_xor_sync(0xffffffffu, ls, 2, 16);
            ls += __shfl_xor_sync(0xffffffffu, ls, 1, 16);
            l[i] = l[i] * f + ls;
            m[i] = mn;
#pragma unroll
            for (int j = 0; j < 4; j++) O[i][j] *= f;
            float* pr = Ps + (qr + i) * 65 + kc;
            pr[0] = S[i][0]; pr[1] = S[i][1]; pr[2] = S[i][2]; pr[3] = S[i][3];
        }
        __syncthreads();

#pragma unroll 4
        for (int k = 0; k < 64; k++) {
            float v0 = Vs[k*65 + kc + 0];
            float v1 = Vs[k*65 + kc + 1];
            float v2 = Vs[k*65 + kc + 2];
            float v3 = Vs[k*65 + kc + 3];
#pragma unroll
            for (int i = 0; i < 8; i++) {
                float p = Ps[(qr+i)*65 + k];
                O[i][0] = fmaf(p, v0, O[i][0]);
                O[i][1] = fmaf(p, v1, O[i][1]);
                O[i][2] = fmaf(p, v2, O[i][2]);
                O[i][3] = fmaf(p, v3, O[i][3]);
            }
        }
        __syncthreads();
    }

    float one_minus_c = 1.0f - cg;
#pragma unroll
    for (int i = 0; i < 8; i++) {
        float inv = 1.0f / l[i];
        int q = q0 + qr + i;
#pragma unroll
        for (int j = 0; j < 4; j++) {
            int dk = kc + j;
            float v = cg * O[i][j] * inv + one_minus_c * vmean[bh * DKK + dk];
            size_t idx = ((size_t)b * TT + q) * DD + h * DKK + dk;
            __nv_bfloat16 hh = __float2bfloat16(v);
            outH[idx] = hh;
            outL[idx] = __float2bfloat16(v - __bfloat162float(hh));
        }
    }
}

// ---------------------------------------------------------------------------
extern "C" void kernel_launch(void* const* d_in, const int* in_sizes, int n_in,
                              void* d_out, int out_size) {
    const float* x   = (const float*)d_in[0];
    const float* Wq  = (const float*)d_in[1];
    const float* bq  = (const float*)d_in[2];
    const float* Wk  = (const float*)d_in[3];
    const float* bk  = (const float*)d_in[4];
    const float* Wv  = (const float*)d_in[5];
    const float* bv  = (const float*)d_in[6];
    const float* Wo  = (const float*)d_in[7];
    const float* bo  = (const float*)d_in[8];
    const float* Wg1 = (const float*)d_in[9];
    const float* bg1 = (const float*)d_in[10];
    const float* Wg2 = (const float*)d_in[11];
    const float* bg2 = (const float*)d_in[12];
    float* out = (float*)d_out;

    float *pQ, *pK, *pV, *pVm, *pC, *pS;
    __nv_bfloat16 *pxh, *pxl, *pWhQ, *pWlQ, *pWhK, *pWlK, *pWhV, *pWlV, *pWhO, *pWlO, *paH, *paL;
    cudaGetSymbolAddress((void**)&pQ, g_Q);
    cudaGetSymbolAddress((void**)&pK, g_K);
    cudaGetSymbolAddress((void**)&pV, g_V);
    cudaGetSymbolAddress((void**)&pVm, g_vmean);
    cudaGetSymbolAddress((void**)&pC, g_c);
    cudaGetSymbolAddress((void**)&pS, g_scale);
    cudaGetSymbolAddress((void**)&pxh, g_xh);
    cudaGetSymbolAddress((void**)&pxl, g_xl);
    cudaGetSymbolAddress((void**)&pWhQ, g_WhQ);
    cudaGetSymbolAddress((void**)&pWlQ, g_WlQ);
    cudaGetSymbolAddress((void**)&pWhK, g_WhK);
    cudaGetSymbolAddress((void**)&pWlK, g_WlK);
    cudaGetSymbolAddress((void**)&pWhV, g_WhV);
    cudaGetSymbolAddress((void**)&pWlV, g_WlV);
    cudaGetSymbolAddress((void**)&pWhO, g_WhO);
    cudaGetSymbolAddress((void**)&pWlO, g_WlO);
    cudaGetSymbolAddress((void**)&paH, g_aH);
    cudaGetSymbolAddress((void**)&paL, g_aL);

    // conversions
    convert_hl<<<(MROWS*DD/4 + 255)/256, 256>>>(x,  pxh,  pxl,  MROWS*DD/4);
    convert_hl<<<(DD*DD/4 + 255)/256, 256>>>(Wq, pWhQ, pWlQ, DD*DD/4);
    convert_hl<<<(DD*DD/4 + 255)/256, 256>>>(Wk, pWhK, pWlK, DD*DD/4);
    convert_hl<<<(DD*DD/4 + 255)/256, 256>>>(Wv, pWhV, pWlV, DD*DD/4);
    convert_hl<<<(DD*DD/4 + 255)/256, 256>>>(Wo, pWhO, pWlO, DD*DD/4);

    const int GEMM_SMEM = 131072;  // 2 stages x 64KB
    cudaFuncSetAttribute(gemm_mma<1>, cudaFuncAttributeMaxDynamicSharedMemorySize, GEMM_SMEM);
    cudaFuncSetAttribute(gemm_mma<0>, cudaFuncAttributeMaxDynamicSharedMemorySize, GEMM_SMEM);

    GemmArgs qkv;
    qkv.Ah = pxh; qkv.Al = pxl;
    qkv.Wh0 = pWhQ; qkv.Wl0 = pWlQ; qkv.Wh1 = pWhK; qkv.Wl1 = pWlK; qkv.Wh2 = pWhV; qkv.Wl2 = pWlV;
    qkv.b0 = bq; qkv.b1 = bk; qkv.b2 = bv;
    qkv.C0 = pQ; qkv.C1 = pK; qkv.C2 = pV;
    dim3 qkv_grid(DD/128, MROWS/128, 3);        // (8, 32, 3)
    gemm_mma<1><<<qkv_grid, 256, GEMM_SMEM>>>(qkv);

    int write_u = (out_size >= BB*TT*DD + BB) ? 1 : 0;
    gate_kernel<<<BB, 256>>>(pQ, Wg1, bg1, Wg2, bg2, pC, pS,
                             out + (size_t)BB*TT*DD, write_u);
    vmean_kernel<<<BB*HH, 256>>>(pV, pVm);

    const int attn_smem = (128*65 + 128*65 + 64*65 + 64*65) * 4;  // 99840 B
    cudaFuncSetAttribute(attn_kernel, cudaFuncAttributeMaxDynamicSharedMemorySize, attn_smem);
    dim3 attn_grid(TT/128, BB*HH);
    attn_kernel<<<attn_grid, 256, attn_smem>>>(pQ, pK, pV, pVm, pC, pS, paH, paL);

    GemmArgs oproj;
    oproj.Ah = paH; oproj.Al = paL;
    oproj.Wh0 = pWhO; oproj.Wl0 = pWlO; oproj.Wh1 = pWhO; oproj.Wl1 = pWlO; oproj.Wh2 = pWhO; oproj.Wl2 = pWlO;
    oproj.b0 = bo; oproj.b1 = bo; oproj.b2 = bo;
    oproj.C0 = out; oproj.C1 = out; oproj.C2 = out;
    dim3 o_grid(DD/128, MROWS/128, 1);          // (8, 32, 1)
    gemm_mma<0><<<o_grid, 256, GEMM_SMEM>>>(oproj);
}

// round 5
// speedup vs baseline: 2.9122x; 1.6103x over previous
#include <cuda_runtime.h>
#include <cuda_bf16.h>
#include <math.h>
#include <stdint.h>

#define BB 4
#define TT 1024
#define DD 1024
#define HH 16
#define DKK 64
#define MROWS (BB*TT)   // 4096

// ---------------- scratch (static device globals) ----------------
__device__ __nv_bfloat16 g_Qh[BB*HH*TT*DKK], g_Ql[BB*HH*TT*DKK];
__device__ __nv_bfloat16 g_Kh[BB*HH*TT*DKK], g_Kl[BB*HH*TT*DKK];
__device__ __nv_bfloat16 g_Vh[BB*HH*TT*DKK], g_Vl[BB*HH*TT*DKK];
__device__ float g_vmean[BB*HH*DKK];
__device__ float g_c[BB];
__device__ float g_scale[BB];
__device__ __nv_bfloat16 g_xh[MROWS*DD], g_xl[MROWS*DD];
__device__ __nv_bfloat16 g_WhQ[DD*DD], g_WlQ[DD*DD];
__device__ __nv_bfloat16 g_WhK[DD*DD], g_WlK[DD*DD];
__device__ __nv_bfloat16 g_WhV[DD*DD], g_WlV[DD*DD];
__device__ __nv_bfloat16 g_WhO[DD*DD], g_WlO[DD*DD];
__device__ __nv_bfloat16 g_aH[MROWS*DD], g_aL[MROWS*DD];

// ---------------- PTX helpers (sm_80-era only) ----------------
__device__ __forceinline__ uint32_t smem_u32(const void* p) {
    uint32_t a;
    asm("{ .reg .u64 t; cvta.to.shared.u64 t, %1; cvt.u32.u64 %0, t; }" : "=r"(a) : "l"(p));
    return a;
}
#define CP_ASYNC16(dst, src) asm volatile("cp.async.cg.shared.global [%0], [%1], 16;" :: "r"(dst), "l"(src))
#define CP_COMMIT()          asm volatile("cp.async.commit_group;" ::: "memory")
#define CP_WAIT(n)           asm volatile("cp.async.wait_group %0;" :: "n"(n) : "memory")

__device__ __forceinline__ void ldsm_x4(uint32_t& r0, uint32_t& r1, uint32_t& r2, uint32_t& r3, uint32_t addr) {
    asm volatile("ldmatrix.sync.aligned.m8n8.x4.shared.b16 {%0,%1,%2,%3}, [%4];"
                 : "=r"(r0), "=r"(r1), "=r"(r2), "=r"(r3) : "r"(addr));
}
__device__ __forceinline__ void ldsm_x2(uint32_t& r0, uint32_t& r1, uint32_t addr) {
    asm volatile("ldmatrix.sync.aligned.m8n8.x2.shared.b16 {%0,%1}, [%2];"
                 : "=r"(r0), "=r"(r1) : "r"(addr));
}
__device__ __forceinline__ void ldsm_x2t(uint32_t& r0, uint32_t& r1, uint32_t addr) {
    asm volatile("ldmatrix.sync.aligned.m8n8.x2.trans.shared.b16 {%0,%1}, [%2];"
                 : "=r"(r0), "=r"(r1) : "r"(addr));
}
__device__ __forceinline__ void mma16816(float* d, const uint32_t* a, const uint32_t* b) {
    asm volatile("mma.sync.aligned.m16n8k16.row.col.f32.bf16.bf16.f32 "
                 "{%0,%1,%2,%3},{%4,%5,%6,%7},{%8,%9},{%0,%1,%2,%3};"
                 : "+f"(d[0]), "+f"(d[1]), "+f"(d[2]), "+f"(d[3])
                 : "r"(a[0]), "r"(a[1]), "r"(a[2]), "r"(a[3]), "r"(b[0]), "r"(b[1]));
}

// ---------------------------------------------------------------------------
// Split-bf16 warp-MMA GEMM: C[m,n] = sum_k A[m,k]*W[n,k] + bias[n]
// MODE 0: C fp32 rowmajor.  MODE 1: split-bf16 hi/lo scatter to [B,H,T,DK].
// ---------------------------------------------------------------------------
struct GemmArgs {
    const __nv_bfloat16 *Ah, *Al;
    const __nv_bfloat16 *Wh0, *Wl0, *Wh1, *Wl1, *Wh2, *Wl2;
    const float *b0, *b1, *b2;
    float *C0;                                       // MODE 0
    __nv_bfloat16 *Ch0, *Cl0, *Ch1, *Cl1, *Ch2, *Cl2; // MODE 1
};

__device__ __forceinline__ void load_stage(uint32_t sbase, int tid,
                                           const __nv_bfloat16* Ah, const __nv_bfloat16* Al,
                                           const __nv_bfloat16* Wh, const __nv_bfloat16* Wl,
                                           int bm, int bn, int k0) {
#pragma unroll
    for (int i = 0; i < 4; i++) {
        int g = tid + i * 256;
        int r = g >> 3;
        int c = g & 7;
        uint32_t sw = (uint32_t)(r * 128 + (((c ^ (r & 7))) << 4));
        size_t ga = (size_t)(bm + r) * 1024 + k0;
        size_t gw = (size_t)(bn + r) * 1024 + k0;
        CP_ASYNC16(sbase +     0 + sw, (const char*)(Ah + ga) + c * 16);
        CP_ASYNC16(sbase + 16384 + sw, (const char*)(Al + ga) + c * 16);
        CP_ASYNC16(sbase + 32768 + sw, (const char*)(Wh + gw) + c * 16);
        CP_ASYNC16(sbase + 49152 + sw, (const char*)(Wl + gw) + c * 16);
    }
}

__device__ __forceinline__ void compute_stage(uint32_t base, int wm, int wn, int lane,
                                              float acc[4][4][4]) {
    const uint32_t aH = base, aL = base + 16384, bH = base + 32768, bL = base + 49152;
    const int rA = wm + (lane & 15);
    const int hA = lane >> 4;
    const int rB = wn + (lane & 7);
    const int hB = (lane >> 3) & 1;
#pragma unroll
    for (int ks = 0; ks < 4; ks++) {
        uint32_t Af[4][4], Alf[4][4], Bf[4][2], Blf[4][2];
#pragma unroll
        for (int mt = 0; mt < 4; mt++) {
            int r = rA + mt * 16;
            uint32_t off = (uint32_t)(r * 128 + ((((ks * 2 + hA)) ^ (r & 7)) << 4));
            ldsm_x4(Af[mt][0], Af[mt][1], Af[mt][2], Af[mt][3], aH + off);
            ldsm_x4(Alf[mt][0], Alf[mt][1], Alf[mt][2], Alf[mt][3], aL + off);
        }
#pragma unroll
        for (int nt = 0; nt < 4; nt++) {
            int r = rB + nt * 8;
            uint32_t off = (uint32_t)(r * 128 + ((((ks * 2 + hB)) ^ (r & 7)) << 4));
            ldsm_x2(Bf[nt][0], Bf[nt][1], bH + off);
            ldsm_x2(Blf[nt][0], Blf[nt][1], bL + off);
        }
#pragma unroll
        for (int mt = 0; mt < 4; mt++)
#pragma unroll
            for (int nt = 0; nt < 4; nt++) {
                mma16816(acc[mt][nt], Af[mt], Bf[nt]);
                mma16816(acc[mt][nt], Af[mt], Blf[nt]);
                mma16816(acc[mt][nt], Alf[mt], Bf[nt]);
            }
    }
}

template<int MODE>
__global__ __launch_bounds__(256)
void gemm_mma(GemmArgs args) {
    extern __shared__ char smem[];
    const int tid = threadIdx.x, wid = tid >> 5, lane = tid & 31;
    const int z = blockIdx.z;
    const __nv_bfloat16* Ah = args.Ah;
    const __nv_bfloat16* Al = args.Al;
    const __nv_bfloat16* Wh = (z == 0) ? args.Wh0 : (z == 1) ? args.Wh1 : args.Wh2;
    const __nv_bfloat16* Wl = (z == 0) ? args.Wl0 : (z == 1) ? args.Wl1 : args.Wl2;
    const float* bias = (z == 0) ? args.b0 : (z == 1) ? args.b1 : args.b2;
    __nv_bfloat16* Ch = (z == 0) ? args.Ch0 : (z == 1) ? args.Ch1 : args.Ch2;
    __nv_bfloat16* Cl = (z == 0) ? args.Cl0 : (z == 1) ? args.Cl1 : args.Cl2;

    const int bm = blockIdx.y * 128, bn = blockIdx.x * 128;
    const int wm = (wid >> 2) * 64, wn = (wid & 3) * 32;
    const uint32_t s0 = smem_u32(smem);

    float acc[4][4][4];
#pragma unroll
    for (int a = 0; a < 4; a++)
#pragma unroll
        for (int b = 0; b < 4; b++)
#pragma unroll
            for (int c = 0; c < 4; c++) acc[a][b][c] = 0.f;

    load_stage(s0, tid, Ah, Al, Wh, Wl, bm, bn, 0);
    CP_COMMIT();

    for (int kt = 0; kt < 16; kt++) {
        const int s = kt & 1;
        if (kt + 1 < 16) {
            load_stage(s0 + ((kt + 1) & 1) * 65536, tid, Ah, Al, Wh, Wl, bm, bn, (kt + 1) * 64);
            CP_COMMIT();
            CP_WAIT(1);
        } else {
            CP_WAIT(0);
        }
        __syncthreads();
        compute_stage(s0 + s * 65536, wm, wn, lane, acc);
        __syncthreads();
    }

    const int lr = lane >> 2, lc = (lane & 3) * 2;
#pragma unroll
    for (int mt = 0; mt < 4; mt++) {
#pragma unroll
        for (int nt = 0; nt < 4; nt++) {
            int c0 = bn + wn + nt * 8 + lc;
            float b0 = __ldg(bias + c0), b1 = __ldg(bias + c0 + 1);
            int r0 = bm + wm + mt * 16 + lr;
            int r1 = r0 + 8;
            float v00 = acc[mt][nt][0] + b0, v01 = acc[mt][nt][1] + b1;
            float v10 = acc[mt][nt][2] + b0, v11 = acc[mt][nt][3] + b1;
            if (MODE == 0) {
                *(float2*)(args.C0 + (size_t)r0 * 1024 + c0) = make_float2(v00, v01);
                *(float2*)(args.C0 + (size_t)r1 * 1024 + c0) = make_float2(v10, v11);
            } else {
                int h = c0 >> 6, dk = c0 & 63;
                size_t i0 = (((size_t)((r0 >> 10) * HH + h)) * TT + (r0 & 1023)) * DKK + dk;
                size_t i1 = (((size_t)((r1 >> 10) * HH + h)) * TT + (r1 & 1023)) * DKK + dk;
                __nv_bfloat162 h0 = __floats2bfloat162_rn(v00, v01);
                __nv_bfloat162 h1 = __floats2bfloat162_rn(v10, v11);
                *(__nv_bfloat162*)(Ch + i0) = h0;
                *(__nv_bfloat162*)(Ch + i1) = h1;
                *(__nv_bfloat162*)(Cl + i0) = __floats2bfloat162_rn(
                    v00 - __bfloat162float(h0.x), v01 - __bfloat162float(h0.y));
                *(__nv_bfloat162*)(Cl + i1) = __floats2bfloat162_rn(
                    v10 - __bfloat162float(h1.x), v11 - __bfloat162float(h1.y));
            }
        }
    }
}

// ---------------------------------------------------------------------------
__global__ void convert_hl(const float* __restrict__ src,
                           __nv_bfloat16* __restrict__ h,
                           __nv_bfloat16* __restrict__ l, int n4) {
    int i = blockIdx.x * 256 + threadIdx.x;
    if (i >= n4) return;
    float4 v = ((const float4*)src)[i];
    __nv_bfloat16 h0 = __float2bfloat16(v.x);
    __nv_bfloat16 h1 = __float2bfloat16(v.y);
    __nv_bfloat16 h2 = __float2bfloat16(v.z);
    __nv_bfloat16 h3 = __float2bfloat16(v.w);
    __nv_bfloat162 hp0; hp0.x = h0; hp0.y = h1;
    __nv_bfloat162 hp1; hp1.x = h2; hp1.y = h3;
    ((__nv_bfloat162*)h)[i * 2 + 0] = hp0;
    ((__nv_bfloat162*)h)[i * 2 + 1] = hp1;
    __nv_bfloat162 lp0, lp1;
    lp0.x = __float2bfloat16(v.x - __bfloat162float(h0));
    lp0.y = __float2bfloat16(v.y - __bfloat162float(h1));
    lp1.x = __float2bfloat16(v.z - __bfloat162float(h2));
    lp1.y = __float2bfloat16(v.w - __bfloat162float(h3));
    ((__nv_bfloat162*)l)[i * 2 + 0] = lp0;
    ((__nv_bfloat162*)l)[i * 2 + 1] = lp1;
}

// ---------------------------------------------------------------------------
__global__ void gate_kernel(const __nv_bfloat16* __restrict__ Qh,
                            const __nv_bfloat16* __restrict__ Ql,
                            const float* __restrict__ Wg1, const float* __restrict__ bg1,
                            const float* __restrict__ Wg2, const float* __restrict__ bg2,
                            float* __restrict__ c_out, float* __restrict__ scale_out,
                            float* __restrict__ u_out, int write_u) {
    int b = blockIdx.x;
    float s1 = 0.f, s2 = 0.f;
    for (int d = threadIdx.x; d < DD; d += 256) {
        size_t idx = ((size_t)(b*HH + (d >> 6)))*TT*DKK + (d & 63);
        float q = __bfloat162float(Qh[idx]) + __bfloat162float(Ql[idx]);
        s1 += q * Wg1[d];
        s2 += q * Wg2[d];
    }
#pragma unroll
    for (int off = 16; off >= 1; off >>= 1) {
        s1 += __shfl_xor_sync(0xffffffffu, s1, off);
        s2 += __shfl_xor_sync(0xffffffffu, s2, off);
    }
    __shared__ float r1[8], r2[8];
    int lane = threadIdx.x & 31, w = threadIdx.x >> 5;
    if (lane == 0) { r1[w] = s1; r2[w] = s2; }
    __syncthreads();
    if (threadIdx.x == 0) {
        float t1 = 0.f, t2 = 0.f;
        for (int i = 0; i < 8; i++) { t1 += r1[i]; t2 += r2[i]; }
        float z1 = t1 + bg1[0], z2 = t2 + bg2[0];
        float q1 = 1.f / (1.f + expf(-z1));
        float q2 = 1.f / (1.f + expf(-z2));
        float c = fminf(fmaxf(q1 * q2, 1e-8f), 1.0f);
        float tau = (c < 0.3f) ? (1.0f / c) : 1.0f;
        c_out[b] = c;
        scale_out[b] = 1.0f / (8.0f * tau);
        if (write_u) u_out[b] = 1.0f - c;
    }
}

// ---------------------------------------------------------------------------
__global__ void vmean_kernel(const __nv_bfloat16* __restrict__ Vh,
                             const __nv_bfloat16* __restrict__ Vl,
                             float* __restrict__ vmean) {
    __shared__ float sm[256];
    int bh = blockIdx.x, tid = threadIdx.x;
    int dk = tid & 63, part = tid >> 6;
    size_t base = (size_t)bh * TT * DKK;
    float s = 0.f;
    for (int t = part; t < TT; t += 4) {
        size_t i = base + (size_t)t * DKK + dk;
        s += __bfloat162float(Vh[i]) + __bfloat162float(Vl[i]);
    }
    sm[tid] = s;
    __syncthreads();
    if (part == 0)
        vmean[bh*DKK + dk] = (sm[dk] + sm[64+dk] + sm[128+dk] + sm[192+dk]) * (1.0f/1024.0f);
}

// ---------------------------------------------------------------------------
// Tensor-core flash attention. Block = 128 queries x (b,h). 8 warps x 16 rows.
// S = QhKh+QhKl+QlKh; PV = PhVh+PhVl+PlVh. Split-bf16 output for O-proj.
// SMEM: Qh@0, Ql@16K; stages at 32K: per stage {Kh@0,Kl@8K,Vh@16K,Vl@24K}, 32K each.
// ---------------------------------------------------------------------------
__global__ __launch_bounds__(256)
void attn_mma(const __nv_bfloat16* __restrict__ Qh, const __nv_bfloat16* __restrict__ Ql,
              const __nv_bfloat16* __restrict__ Kh, const __nv_bfloat16* __restrict__ Kl,
              const __nv_bfloat16* __restrict__ Vh, const __nv_bfloat16* __restrict__ Vl,
              const float* __restrict__ vmean,
              const float* __restrict__ c_arr, const float* __restrict__ scale_arr,
              __nv_bfloat16* __restrict__ outH, __nv_bfloat16* __restrict__ outL) {
    extern __shared__ char smem[];
    const int tid = threadIdx.x, wid = tid >> 5, lane = tid & 31;
    const int bh = blockIdx.y;
    const int b = bh >> 4, h = bh & 15;
    const int q0 = blockIdx.x * 128;
    const float scale = scale_arr[b];
    const float cg = c_arr[b];
    const size_t gbase = (size_t)bh * TT * DKK;

    const uint32_t s0 = smem_u32(smem);
    const uint32_t QH = s0, QL = s0 + 16384;
    const uint32_t ST = s0 + 32768;

    // ---- load Q tile (both halves) + KV stage 0, one cp.async group ----
#pragma unroll
    for (int i = 0; i < 8; i++) {
        int g = tid + i * 256;              // 0..2047
        int arr = g >> 10;                  // 0: Qh, 1: Ql
        int rem = g & 1023;
        int r = rem >> 3, c = rem & 7;
        uint32_t sw = (uint32_t)(r * 128 + ((c ^ (r & 7)) << 4));
        const __nv_bfloat16* src = arr ? Ql : Qh;
        CP_ASYNC16((arr ? QL : QH) + sw, (const char*)(src + gbase + (size_t)(q0 + r) * 64) + c * 16);
    }
#pragma unroll
    for (int i = 0; i < 8; i++) {
        int g = tid + i * 256;              // 0..2047
        int arr = g >> 9;                   // 0:Kh 1:Kl 2:Vh 3:Vl
        int rem = g & 511;
        int r = rem >> 3, c = rem & 7;
        uint32_t sw = (uint32_t)(r * 128 + ((c ^ (r & 7)) << 4));
        const __nv_bfloat16* src = (arr == 0) ? Kh : (arr == 1) ? Kl : (arr == 2) ? Vh : Vl;
        CP_ASYNC16(ST + arr * 8192 + sw, (const char*)(src + gbase + (size_t)r * 64) + c * 16);
    }
    CP_COMMIT();

    // fragment index helpers
    const int rA = wid * 16 + (lane & 15);   // Q A-frag row (within 128-tile)
    const int hA = lane >> 4;
    const int rB = lane & 7;                 // K B-frag row base
    const int hB = (lane >> 3) & 1;
    const int rV = lane & 15;                // V trans-frag row base

    uint32_t qhF[4][4], qlF[4][4];
    float O[8][4];
    float m0 = -1e30f, m1 = -1e30f, l0 = 0.f, l1 = 0.f;
#pragma unroll
    for (int nt = 0; nt < 8; nt++)
#pragma unroll
        for (int j = 0; j < 4; j++) O[nt][j] = 0.f;

    for (int kt = 0; kt < 16; kt++) {
        const uint32_t stage = ST + (kt & 1) * 32768;
        // prefetch next stage
        if (kt + 1 < 16) {
            const uint32_t nstage = ST + ((kt + 1) & 1) * 32768;
            const int k0n = (kt + 1) * 64;
#pragma unroll
            for (int i = 0; i < 8; i++) {
                int g = tid + i * 256;
                int arr = g >> 9;
                int rem = g & 511;
                int r = rem >> 3, c = rem & 7;
                uint32_t sw = (uint32_t)(r * 128 + ((c ^ (r & 7)) << 4));
                const __nv_bfloat16* src = (arr == 0) ? Kh : (arr == 1) ? Kl : (arr == 2) ? Vh : Vl;
                CP_ASYNC16(nstage + arr * 8192 + sw,
                           (const char*)(src + gbase + (size_t)(k0n + r) * 64) + c * 16);
            }
            CP_COMMIT();
            CP_WAIT(1);
        } else {
            CP_WAIT(0);
        }
        __syncthreads();

        if (kt == 0) {
            // hoist Q fragments (constant across kv loop)
#pragma unroll
            for (int ks = 0; ks < 4; ks++) {
                uint32_t off = (uint32_t)(rA * 128 + (((ks * 2 + hA) ^ (rA & 7)) << 4));
                ldsm_x4(qhF[ks][0], qhF[ks][1], qhF[ks][2], qhF[ks][3], QH + off);
                ldsm_x4(qlF[ks][0], qlF[ks][1], qlF[ks][2], qlF[ks][3], QL + off);
            }
        }

        // ---- S = Q K^T (3-term split) ----
        float sacc[8][4];
#pragma unroll
        for (int nt = 0; nt < 8; nt++)
#pragma unroll
            for (int j = 0; j < 4; j++) sacc[nt][j] = 0.f;

        const uint32_t KHs = stage, KLs = stage + 8192;
#pragma unroll
        for (int ks = 0; ks < 4; ks++) {
#pragma unroll
            for (int nt = 0; nt < 8; nt++) {
                int r = nt * 8 + rB;
                uint32_t off = (uint32_t)(r * 128 + (((ks * 2 + hB) ^ (r & 7)) << 4));
                uint32_t kh[2], kl[2];
                ldsm_x2(kh[0], kh[1], KHs + off);
                ldsm_x2(kl[0], kl[1], KLs + off);
                mma16816(sacc[nt], qhF[ks], kh);
                mma16816(sacc[nt], qhF[ks], kl);
                mma16816(sacc[nt], qlF[ks], kh);
            }
        }

        // ---- online softmax (rows r0 = lane>>2, r1 = r0+8) ----
        float mx0 = -1e30f, mx1 = -1e30f;
#pragma unroll
        for (int nt = 0; nt < 8; nt++) {
            mx0 = fmaxf(mx0, fmaxf(sacc[nt][0], sacc[nt][1]));
            mx1 = fmaxf(mx1, fmaxf(sacc[nt][2], sacc[nt][3]));
        }
        mx0 = fmaxf(mx0, __shfl_xor_sync(0xffffffffu, mx0, 1));
        mx0 = fmaxf(mx0, __shfl_xor_sync(0xffffffffu, mx0, 2));
        mx1 = fmaxf(mx1, __shfl_xor_sync(0xffffffffu, mx1, 1));
        mx1 = fmaxf(mx1, __shfl_xor_sync(0xffffffffu, mx1, 2));
        float mn0 = fmaxf(m0, mx0 * scale);
        float mn1 = fmaxf(m1, mx1 * scale);
        float f0 = __expf(m0 - mn0), f1 = __expf(m1 - mn1);
        m0 = mn0; m1 = mn1;

        float rs0 = 0.f, rs1 = 0.f;
#pragma unroll
        for (int nt = 0; nt < 8; nt++) {
            sacc[nt][0] = __expf(fmaf(sacc[nt][0], scale, -mn0));
            sacc[nt][1] = __expf(fmaf(sacc[nt][1], scale, -mn0));
            sacc[nt][2] = __expf(fmaf(sacc[nt][2], scale, -mn1));
            sacc[nt][3] = __expf(fmaf(sacc[nt][3], scale, -mn1));
            rs0 += sacc[nt][0] + sacc[nt][1];
            rs1 += sacc[nt][2] + sacc[nt][3];
        }
        rs0 += __shfl_xor_sync(0xffffffffu, rs0, 1);
        rs0 += __shfl_xor_sync(0xffffffffu, rs0, 2);
        rs1 += __shfl_xor_sync(0xffffffffu, rs1, 1);
        rs1 += __shfl_xor_sync(0xffffffffu, rs1, 2);
        l0 = l0 * f0 + rs0;
        l1 = l1 * f1 + rs1;
#pragma unroll
        for (int nt = 0; nt < 8; nt++) {
            O[nt][0] *= f0; O[nt][1] *= f0;
            O[nt][2] *= f1; O[nt][3] *= f1;
        }

        // ---- O += P V (3-term split), P frags from sacc ----
        const uint32_t VHs = stage + 16384, VLs = stage + 24576;
#pragma unroll
        for (int pk = 0; pk < 4; pk++) {
            uint32_t ph[4], pl[4];
#pragma unroll
            for (int half = 0; half < 2; half++) {
                int nt = 2 * pk + half;
                __nv_bfloat162 a0 = __floats2bfloat162_rn(sacc[nt][0], sacc[nt][1]);
                __nv_bfloat162 a1 = __floats2bfloat162_rn(sacc[nt][2], sacc[nt][3]);
                ph[2*half + 0] = *(uint32_t*)&a0;
                ph[2*half + 1] = *(uint32_t*)&a1;
                __nv_bfloat162 b0 = __floats2bfloat162_rn(
                    sacc[nt][0] - __bfloat162float(a0.x), sacc[nt][1] - __bfloat162float(a0.y));
                __nv_bfloat162 b1 = __floats2bfloat162_rn(
                    sacc[nt][2] - __bfloat162float(a1.x), sacc[nt][3] - __bfloat162float(a1.y));
                pl[2*half + 0] = *(uint32_t*)&b0;
                pl[2*half + 1] = *(uint32_t*)&b1;
            }
            int r = pk * 16 + rV;
#pragma unroll
            for (int nt = 0; nt < 8; nt++) {
                uint32_t off = (uint32_t)(r * 128 + ((nt ^ (r & 7)) << 4));
                uint32_t vh[2], vl[2];
                ldsm_x2t(vh[0], vh[1], VHs + off);
                ldsm_x2t(vl[0], vl[1], VLs + off);
                mma16816(O[nt], ph, vh);
                mma16816(O[nt], ph, vl);
                mma16816(O[nt], pl, vh);
            }
        }
        __syncthreads();
    }

    // ---- epilogue: gate + vmean, split-bf16 output for O-projection ----
    const float inv0 = 1.0f / l0, inv1 = 1.0f / l1;
    const float omc = 1.0f - cg;
    const int row0 = q0 + wid * 16 + (lane >> 2);
    const int row1 = row0 + 8;
#pragma unroll
    for (int nt = 0; nt < 8; nt++) {
        int dk = nt * 8 + (lane & 3) * 2;
        float vm0 = vmean[bh * DKK + dk], vm1 = vmean[bh * DKK + dk + 1];
        float o00 = cg * O[nt][0] * inv0 + omc * vm0;
        float o01 = cg * O[nt][1] * inv0 + omc * vm1;
        float o10 = cg * O[nt][2] * inv1 + omc * vm0;
        float o11 = cg * O[nt][3] * inv1 + omc * vm1;
        size_t i0 = ((size_t)b * TT + row0) * DD + h * DKK + dk;
        size_t i1 = ((size_t)b * TT + row1) * DD + h * DKK + dk;
        __nv_bfloat162 h0 = __floats2bfloat162_rn(o00, o01);
        __nv_bfloat162 h1 = __floats2bfloat162_rn(o10, o11);
        *(__nv_bfloat162*)(outH + i0) = h0;
        *(__nv_bfloat162*)(outH + i1) = h1;
        *(__nv_bfloat162*)(outL + i0) = __floats2bfloat162_rn(
            o00 - __bfloat162float(h0.x), o01 - __bfloat162float(h0.y));
        *(__nv_bfloat162*)(outL + i1) = __floats2bfloat162_rn(
            o10 - __bfloat162float(h1.x), o11 - __bfloat162float(h1.y));
    }
}

// ---------------------------------------------------------------------------
extern "C" void kernel_launch(void* const* d_in, const int* in_sizes, int n_in,
                              void* d_out, int out_size) {
    const float* x   = (const float*)d_in[0];
    const float* Wq  = (const float*)d_in[1];
    const float* bq  = (const float*)d_in[2];
    const float* Wk  = (const float*)d_in[3];
    const float* bk  = (const float*)d_in[4];
    const float* Wv  = (const float*)d_in[5];
    const float* bv  = (const float*)d_in[6];
    const float* Wo  = (const float*)d_in[7];
    const float* bo  = (const float*)d_in[8];
    const float* Wg1 = (const float*)d_in[9];
    const float* bg1 = (const float*)d_in[10];
    const float* Wg2 = (const float*)d_in[11];
    const float* bg2 = (const float*)d_in[12];
    float* out = (float*)d_out;

    float *pVm, *pC, *pS;
    __nv_bfloat16 *pQh, *pQl, *pKh, *pKl, *pVh, *pVl;
    __nv_bfloat16 *pxh, *pxl, *pWhQ, *pWlQ, *pWhK, *pWlK, *pWhV, *pWlV, *pWhO, *pWlO, *paH, *paL;
    cudaGetSymbolAddress((void**)&pQh, g_Qh);
    cudaGetSymbolAddress((void**)&pQl, g_Ql);
    cudaGetSymbolAddress((void**)&pKh, g_Kh);
    cudaGetSymbolAddress((void**)&pKl, g_Kl);
    cudaGetSymbolAddress((void**)&pVh, g_Vh);
    cudaGetSymbolAddress((void**)&pVl, g_Vl);
    cudaGetSymbolAddress((void**)&pVm, g_vmean);
    cudaGetSymbolAddress((void**)&pC, g_c);
    cudaGetSymbolAddress((void**)&pS, g_scale);
    cudaGetSymbolAddress((void**)&pxh, g_xh);
    cudaGetSymbolAddress((void**)&pxl, g_xl);
    cudaGetSymbolAddress((void**)&pWhQ, g_WhQ);
    cudaGetSymbolAddress((void**)&pWlQ, g_WlQ);
    cudaGetSymbolAddress((void**)&pWhK, g_WhK);
    cudaGetSymbolAddress((void**)&pWlK, g_WlK);
    cudaGetSymbolAddress((void**)&pWhV, g_WhV);
    cudaGetSymbolAddress((void**)&pWlV, g_WlV);
    cudaGetSymbolAddress((void**)&pWhO, g_WhO);
    cudaGetSymbolAddress((void**)&pWlO, g_WlO);
    cudaGetSymbolAddress((void**)&paH, g_aH);
    cudaGetSymbolAddress((void**)&paL, g_aL);

    convert_hl<<<(MROWS*DD/4 + 255)/256, 256>>>(x,  pxh,  pxl,  MROWS*DD/4);
    convert_hl<<<(DD*DD/4 + 255)/256, 256>>>(Wq, pWhQ, pWlQ, DD*DD/4);
    convert_hl<<<(DD*DD/4 + 255)/256, 256>>>(Wk, pWhK, pWlK, DD*DD/4);
    convert_hl<<<(DD*DD/4 + 255)/256, 256>>>(Wv, pWhV, pWlV, DD*DD/4);
    convert_hl<<<(DD*DD/4 + 255)/256, 256>>>(Wo, pWhO, pWlO, DD*DD/4);

    const int GEMM_SMEM = 131072;
    cudaFuncSetAttribute(gemm_mma<1>, cudaFuncAttributeMaxDynamicSharedMemorySize, GEMM_SMEM);
    cudaFuncSetAttribute(gemm_mma<0>, cudaFuncAttributeMaxDynamicSharedMemorySize, GEMM_SMEM);

    GemmArgs qkv = {};
    qkv.Ah = pxh; qkv.Al = pxl;
    qkv.Wh0 = pWhQ; qkv.Wl0 = pWlQ; qkv.Wh1 = pWhK; qkv.Wl1 = pWlK; qkv.Wh2 = pWhV; qkv.Wl2 = pWlV;
    qkv.b0 = bq; qkv.b1 = bk; qkv.b2 = bv;
    qkv.Ch0 = pQh; qkv.Cl0 = pQl; qkv.Ch1 = pKh; qkv.Cl1 = pKl; qkv.Ch2 = pVh; qkv.Cl2 = pVl;
    dim3 qkv_grid(DD/128, MROWS/128, 3);
    gemm_mma<1><<<qkv_grid, 256, GEMM_SMEM>>>(qkv);

    int write_u = (out_size >= BB*TT*DD + BB) ? 1 : 0;
    gate_kernel<<<BB, 256>>>(pQh, pQl, Wg1, bg1, Wg2, bg2, pC, pS,
                             out + (size_t)BB*TT*DD, write_u);
    vmean_kernel<<<BB*HH, 256>>>(pVh, pVl, pVm);

    const int ATTN_SMEM = 32768 + 2 * 32768;   // 98304
    cudaFuncSetAttribute(attn_mma, cudaFuncAttributeMaxDynamicSharedMemorySize, ATTN_SMEM);
    dim3 attn_grid(TT/128, BB*HH);
    attn_mma<<<attn_grid, 256, ATTN_SMEM>>>(pQh, pQl, pKh, pKl, pVh, pVl,
                                            pVm, pC, pS, paH, paL);

    GemmArgs oproj = {};
    oproj.Ah = paH; oproj.Al = paL;
    oproj.Wh0 = pWhO; oproj.Wl0 = pWlO; oproj.Wh1 = pWhO; oproj.Wl1 = pWlO; oproj.Wh2 = pWhO; oproj.Wl2 = pWlO;
    oproj.b0 = bo; oproj.b1 = bo; oproj.b2 = bo;
    oproj.C0 = out;
    dim3 o_grid(DD/128, MROWS/128, 1);
    gemm_mma<0><<<o_grid, 256, GEMM_SMEM>>>(oproj);
}